// round 7
// baseline (speedup 1.0000x reference)
#include <cuda_runtime.h>
#include <cstddef>
#include <cstdint>

// Problem shape
#define BATCH 4096
#define FN    1024
#define RC    19
#define RD    1024
#define FLAT  (FN * RC)            // 19456 floats per conv batch row

#define W_SMEM_BYTES (FLAT * 4)    // 77824 B (all of R staged in smem)

#define RING  8                    // cp.async ring stages per warp (512 B each)
#define ITERS 152                  // 19456/128 float4-iterations per batch
                                   // 152 = LCM(8,19): ring slot AND residue slot
                                   // are both compile-time under full unroll

__device__ float g_W[FLAT];        // W[f][r] flat, matches conv's [f*19+r]

// ---------------------------------------------------------------------------
// Kernel 1: W = U @ R^T with R staged in shared memory (unchanged from r5).
// ---------------------------------------------------------------------------
__global__ void compute_w_kernel(const float* __restrict__ U,
                                 const float* __restrict__ R) {
    extern __shared__ float sR[];
    const int tid  = threadIdx.x;
    const int lane = tid & 31;
    const int wid  = tid >> 5;

    {
        float4* s4 = reinterpret_cast<float4*>(sR);
        const float4* g4 = reinterpret_cast<const float4*>(R);
#pragma unroll
        for (int k = 0; k < 19; k++)
            s4[tid + 256 * k] = g4[tid + 256 * k];
    }
    __syncthreads();

    const int f = blockIdx.x * 8 + wid;
    const float4* u4 = reinterpret_cast<const float4*>(U + (size_t)f * RD);
    float4 u[8];
#pragma unroll
    for (int i = 0; i < 8; i++) u[i] = u4[lane + 32 * i];

    for (int r = 0; r < RC; r++) {
        const float4* r4 = reinterpret_cast<const float4*>(sR + (size_t)r * RD);
        float s = 0.f;
#pragma unroll
        for (int i = 0; i < 8; i++) {
            float4 rv = r4[lane + 32 * i];
            s += u[i].x * rv.x + u[i].y * rv.y + u[i].z * rv.z + u[i].w * rv.w;
        }
#pragma unroll
        for (int off = 16; off > 0; off >>= 1)
            s += __shfl_xor_sync(0xffffffffu, s, off);
        if (lane == 0) g_W[f * RC + r] = s;
    }
}

// ---------------------------------------------------------------------------
// Kernel 2: score[b][r] = sum_f conv[b][f][r] * W[f][r]
//
// Warp-per-batch (6/7 Bresenham over 4 blocks/SM, all resident). conv is
// streamed with per-lane cp.async.cg (L1-bypass, zero data registers) into a
// per-warp 8-stage x 512 B shared ring: ~4 KB outstanding per warp, fully
// decoupling memory-level parallelism from the 19 register accumulators.
// Each lane consumes exactly the 16 B it fetched -> cp.async.wait_group is
// the only synchronization. W reads stay __ldg (L1 now holds only W).
//
// Residues: flat idx = i*128 + 4*lane + j, 128 % 19 = 14:
//   r = (14*i + 4*lane + j) mod 19, slot k = (14*i + j) mod 19 (compile-time).
// ---------------------------------------------------------------------------
__global__ __launch_bounds__(256, 4)
void score_kernel(const float* __restrict__ conv, float* __restrict__ out,
                  int k6, int nb) {
    __shared__ float4 ring[8][RING][32];    // [warp][slot][lane] = 32768 B

    const int lane = threadIdx.x & 31;
    const int wid  = threadIdx.x >> 5;
    const int bid  = blockIdx.x;

    // Bresenham 6/7-batch assignment (exact static coverage of 4096 batches).
    const int n6_lo = (int)(((long long)bid * k6) / nb);
    const int n6_hi = (int)(((long long)(bid + 1) * k6) / nb);
    const int cnt   = 7 - (n6_hi - n6_lo);
    const int base  = bid * 7 - n6_lo;
    if (wid >= cnt) return;
    const int b = base + wid;

    const float4* c4 = reinterpret_cast<const float4*>(conv + (size_t)b * FLAT);
    const float4* w4 = reinterpret_cast<const float4*>(g_W);

    const uint32_t rbase =
        (uint32_t)__cvta_generic_to_shared(&ring[wid][0][lane]);

    // Prologue: stages 0..6 in flight.
#pragma unroll
    for (int s = 0; s < RING - 1; s++) {
        uint32_t sa = rbase + (uint32_t)(s * 512);
        const float4* ga = c4 + s * 32 + lane;
        asm volatile("cp.async.cg.shared.global [%0], [%1], 16;\n"
                     :: "r"(sa), "l"(ga) : "memory");
        asm volatile("cp.async.commit_group;\n" ::: "memory");
    }

    float acc[RC];
#pragma unroll
    for (int k = 0; k < RC; k++) acc[k] = 0.f;

#pragma unroll
    for (int i = 0; i < ITERS; i++) {
        // Keep the pipe full: issue stage i+7, then wait for stage i.
        if (i + RING - 1 < ITERS) {
            uint32_t sa = rbase + (uint32_t)(((i + RING - 1) % RING) * 512);
            const float4* ga = c4 + (i + RING - 1) * 32 + lane;
            asm volatile("cp.async.cg.shared.global [%0], [%1], 16;\n"
                         :: "r"(sa), "l"(ga) : "memory");
            asm volatile("cp.async.commit_group;\n" ::: "memory");
            asm volatile("cp.async.wait_group %0;\n" :: "n"(RING - 1) : "memory");
        } else {
            asm volatile("cp.async.wait_all;\n" ::: "memory");   // short tail
        }

        float4 cv = ring[wid][i % RING][lane];        // our own 16 B
        float4 wv = __ldg(&w4[i * 32 + lane]);        // L1-resident

        acc[(14 * i + 0) % RC] += cv.x * wv.x;
        acc[(14 * i + 1) % RC] += cv.y * wv.y;
        acc[(14 * i + 2) % RC] += cv.z * wv.z;
        acc[(14 * i + 3) % RC] += cv.w * wv.w;
    }

    // Butterfly: lane l slot k holds r=(4l+k)%19; peer l+d has it at (k-4d)%19.
#pragma unroll
    for (int d = 16; d >= 1; d >>= 1) {
        float tmp[RC];
#pragma unroll
        for (int k = 0; k < RC; k++) {
            const int s = (k + 4 * RC - 4 * d) % RC;
            tmp[k] = __shfl_down_sync(0xffffffffu, acc[s], d);
        }
#pragma unroll
        for (int k = 0; k < RC; k++) acc[k] += tmp[k];
    }

    // Lane 0: slot k == relation k. Direct stores, no atomics.
    if (lane == 0) {
        float* ob = out + (size_t)b * RC;
#pragma unroll
        for (int k = 0; k < RC; k++) ob[k] = acc[k];
    }
}

// ---------------------------------------------------------------------------
// Launch
// ---------------------------------------------------------------------------
extern "C" void kernel_launch(void* const* d_in, const int* in_sizes, int n_in,
                              void* d_out, int out_size) {
    const float* conv = nullptr;
    const float* R    = nullptr;
    const float* U    = nullptr;
    for (int i = 0; i < n_in; i++) {
        long long n = in_sizes[i];
        if (n == (long long)BATCH * FN * RC)      conv = (const float*)d_in[i];
        else if (n == (long long)RC * RD)         R    = (const float*)d_in[i];
        else if (n == (long long)FN * RD)         U    = (const float*)d_in[i];
    }
    float* out = (float*)d_out;

    int nsm = 148;
    cudaDeviceProp prop;
    if (cudaGetDeviceProperties(&prop, 0) == cudaSuccess)
        nsm = prop.multiProcessorCount;
    if (nsm < 147) nsm = 147;
    if (nsm > 170) nsm = 170;
    const int nb = 4 * nsm;            // 608 on GB300: all blocks resident
    const int k6 = 7 * nb - BATCH;

    cudaFuncSetAttribute(compute_w_kernel,
                         cudaFuncAttributeMaxDynamicSharedMemorySize, W_SMEM_BYTES);
    compute_w_kernel<<<128, 256, W_SMEM_BYTES>>>(U, R);
    score_kernel<<<nb, 256>>>(conv, out, k6, nb);
}

// round 8
// speedup vs baseline: 1.2001x; 1.2001x over previous
#include <cuda_runtime.h>
#include <cstddef>

// Problem shape
#define BATCH 4096
#define FN    1024
#define RC    19
#define RD    1024
#define FLAT  (FN * RC)            // 19456 floats per conv batch row
#define QT_F4 (FLAT / 4 / 4)       // 1216 float4 per quarter (4864 floats = 19*256)

#define W_SMEM_BYTES (FLAT * 4)    // 77824 B (all of R staged in smem)

__device__ float g_W[FLAT];        // W[f][r] flat, matches conv's [f*19+r]

// ---------------------------------------------------------------------------
// Kernel 1: W = U @ R^T with R staged in shared memory.
// 128 blocks x 256 threads; block stages R (76 KB) once, warp i computes
// f = blk*8 + i with its U row in registers. ~14 MB L2 traffic, ~2 us.
// ---------------------------------------------------------------------------
__global__ void compute_w_kernel(const float* __restrict__ U,
                                 const float* __restrict__ R) {
    extern __shared__ float sR[];
    const int tid  = threadIdx.x;
    const int lane = tid & 31;
    const int wid  = tid >> 5;

    {
        float4* s4 = reinterpret_cast<float4*>(sR);
        const float4* g4 = reinterpret_cast<const float4*>(R);
#pragma unroll
        for (int k = 0; k < 19; k++)
            s4[tid + 256 * k] = g4[tid + 256 * k];
    }
    __syncthreads();

    const int f = blockIdx.x * 8 + wid;
    const float4* u4 = reinterpret_cast<const float4*>(U + (size_t)f * RD);
    float4 u[8];
#pragma unroll
    for (int i = 0; i < 8; i++) u[i] = u4[lane + 32 * i];

    for (int r = 0; r < RC; r++) {
        const float4* r4 = reinterpret_cast<const float4*>(sR + (size_t)r * RD);
        float s = 0.f;
#pragma unroll
        for (int i = 0; i < 8; i++) {
            float4 rv = r4[lane + 32 * i];
            s += u[i].x * rv.x + u[i].y * rv.y + u[i].z * rv.z + u[i].w * rv.w;
        }
#pragma unroll
        for (int off = 16; off > 0; off >>= 1)
            s += __shfl_xor_sync(0xffffffffu, s, off);
        if (lane == 0) g_W[f * RC + r] = s;
    }
}

// ---------------------------------------------------------------------------
// Kernel 2: score[b][r] = sum_f conv[b][f][r] * W[f][r]
//
// Warp-per-batch, b = blockIdx.x*8 + wid (the r2 mapping that measured best).
// MLP fix: each warp walks FOUR independent quarter-streams of its batch.
// Quarter = 4864 floats = 19*256 === 0 (mod 19), so all quarters share the
// same residue pattern and accumulate into the SAME 19 compile-time slots.
// Per iteration: 4 back-to-back independent __ldcs LDG.128 (MLP_p1=4, DRAM)
// then 4x (L1-resident W load + 4 FFMA). 38 iterations total.
//
// Residues (within a quarter): flat idx = i*128 + 4*lane + j, 128 % 19 = 14:
//   r = (14*i + 4*lane + j) mod 19, slot k = (14*i + j) mod 19.
// ---------------------------------------------------------------------------
__global__ __launch_bounds__(256, 4)
void score_kernel(const float* __restrict__ conv, float* __restrict__ out) {
    const int lane = threadIdx.x & 31;
    const int b    = blockIdx.x * 8 + (threadIdx.x >> 5);

    const float4* c4 = reinterpret_cast<const float4*>(conv + (size_t)b * FLAT);
    const float4* w4 = reinterpret_cast<const float4*>(g_W);

    float acc[RC];
#pragma unroll
    for (int k = 0; k < RC; k++) acc[k] = 0.f;

    // 38 iterations = 2 outer x 19 inner (slot pattern period 19).
    for (int o = 0; o < 2; o++) {
#pragma unroll
        for (int t = 0; t < 19; t++) {
            const int i   = o * 19 + t;
            const int ofs = i * 32 + lane;

            // 4 independent DRAM streams, front-batched by ptxas.
            float4 cv0 = __ldcs(&c4[ofs]);
            float4 cv1 = __ldcs(&c4[ofs + QT_F4]);
            float4 cv2 = __ldcs(&c4[ofs + 2 * QT_F4]);
            float4 cv3 = __ldcs(&c4[ofs + 3 * QT_F4]);

            const int k0 = (14 * t + 0) % RC;
            const int k1 = (14 * t + 1) % RC;
            const int k2 = (14 * t + 2) % RC;
            const int k3 = (14 * t + 3) % RC;

            float4 wv;
            wv = __ldg(&w4[ofs]);
            acc[k0] += cv0.x * wv.x; acc[k1] += cv0.y * wv.y;
            acc[k2] += cv0.z * wv.z; acc[k3] += cv0.w * wv.w;
            wv = __ldg(&w4[ofs + QT_F4]);
            acc[k0] += cv1.x * wv.x; acc[k1] += cv1.y * wv.y;
            acc[k2] += cv1.z * wv.z; acc[k3] += cv1.w * wv.w;
            wv = __ldg(&w4[ofs + 2 * QT_F4]);
            acc[k0] += cv2.x * wv.x; acc[k1] += cv2.y * wv.y;
            acc[k2] += cv2.z * wv.z; acc[k3] += cv2.w * wv.w;
            wv = __ldg(&w4[ofs + 3 * QT_F4]);
            acc[k0] += cv3.x * wv.x; acc[k1] += cv3.y * wv.y;
            acc[k2] += cv3.z * wv.z; acc[k3] += cv3.w * wv.w;
        }
    }

    // Butterfly: lane l slot k holds r=(4l+k)%19; peer l+d has it at (k-4d)%19.
#pragma unroll
    for (int d = 16; d >= 1; d >>= 1) {
        float tmp[RC];
#pragma unroll
        for (int k = 0; k < RC; k++) {
            const int s = (k + 4 * RC - 4 * d) % RC;
            tmp[k] = __shfl_down_sync(0xffffffffu, acc[s], d);
        }
#pragma unroll
        for (int k = 0; k < RC; k++) acc[k] += tmp[k];
    }

    // Lane 0: slot k == relation k. Direct stores, no atomics.
    if (lane == 0) {
        float* ob = out + (size_t)b * RC;
#pragma unroll
        for (int k = 0; k < RC; k++) ob[k] = acc[k];
    }
}

// ---------------------------------------------------------------------------
// Launch
// ---------------------------------------------------------------------------
extern "C" void kernel_launch(void* const* d_in, const int* in_sizes, int n_in,
                              void* d_out, int out_size) {
    const float* conv = nullptr;
    const float* R    = nullptr;
    const float* U    = nullptr;
    for (int i = 0; i < n_in; i++) {
        long long n = in_sizes[i];
        if (n == (long long)BATCH * FN * RC)      conv = (const float*)d_in[i];
        else if (n == (long long)RC * RD)         R    = (const float*)d_in[i];
        else if (n == (long long)FN * RD)         U    = (const float*)d_in[i];
    }
    float* out = (float*)d_out;

    cudaFuncSetAttribute(compute_w_kernel,
                         cudaFuncAttributeMaxDynamicSharedMemorySize, W_SMEM_BYTES);
    compute_w_kernel<<<128, 256, W_SMEM_BYTES>>>(U, R);
    score_kernel<<<512, 256>>>(conv, out);   // 4096 warps, warp-per-batch
}